// round 16
// baseline (speedup 1.0000x reference)
#include <cuda_runtime.h>

// MakeCutouts: 64 cutouts of [4,3,512,512] fp32 -> bilinear 224x224, out [256,3,224,224].
//
// R15 config (CHUNK=8, PH=6, bound=5, full unroll, 56 regs) with ONE change:
// the fresh-reuse is BRANCH-FREE. `if (fresh)` became predicated loads
// (fresh ? __ldg : 0 -> @P LDG, off-lanes issue no request = 0 wavefronts)
// plus an FSEL for h0. The unrolled 8-iteration body is now a single basic
// block, so ptxas can hoist iteration k+1's address-independent LDGs above
// iteration k's FMA consumers — the cross-iteration pipelining that R15's
// branchy body blocked (BSSY islands).
//
//  - planes split 6+6 (blockIdx.z); per row-step 4 base pointers, plane loads
//    by immediate offset; row iy1 always fresh (strictly increasing), row iy0
//    reused when it equals previous iy1 (warp-uniform predicate).
//  - warp = 32 consecutive j -> coalesced __stcs stores; input stays L2-resident.

#define IMG   512
#define S     224
#define CUTN  64
#define NCH   12
#define PH    6
#define CHUNK 8
#define PLANE (IMG*IMG)
#define OPLANE (S*S)

__global__ __launch_bounds__(S, 5)
void make_cutouts_kernel(const float* __restrict__ x,
                         const int*   __restrict__ sizes,
                         const int*   __restrict__ offsetx,
                         const int*   __restrict__ offsety,
                         float*       __restrict__ out)
{
    const int j     = threadIdx.x;            // output column
    const int i0    = blockIdx.x * CHUNK;     // first output row of this chunk
    const int n     = blockIdx.y;             // cutout
    const int pbase = blockIdx.z * PH;        // plane half (0 or 6)

    const int   size  = __ldg(sizes + n);
    const float scale = (float)size * (1.0f / (float)S);
    const int   ox    = __ldg(offsetx + n);
    const int   oy    = __ldg(offsety + n);
    const int   sm1   = size - 1;

    // column taps (fixed for the whole walk)
    float srcx = fmaxf(scale * ((float)j + 0.5f) - 0.5f, 0.0f);
    int   ix0  = (int)floorf(srcx);
    const float fx = srcx - (float)ix0;       // frac before clamp (matches ref)
    ix0 = min(ix0, sm1);
    const int ix1 = min(ix0 + 1, sm1);
    const float wx1 = fx, wx0 = 1.0f - fx;

    const float* __restrict__ baseA = x + pbase * PLANE + (ox + ix0);
    const float* __restrict__ baseB = x + pbase * PLANE + (ox + ix1);

    float h1v[PH];                            // last blended source row, per plane
    int iy1_prev = -1000000;                  // sentinel: first row loads both

    float* __restrict__ op = out + ((n * NCH + pbase) * OPLANE + i0 * S + j);

    #pragma unroll
    for (int k = 0; k < CHUNK; ++k) {
        const int i = i0 + k;
        float srcy = fmaxf(scale * ((float)i + 0.5f) - 0.5f, 0.0f);
        int   iy0  = (int)floorf(srcy);
        const float fy = srcy - (float)iy0;
        iy0 = min(iy0, sm1);
        const int iy1 = min(iy0 + 1, sm1);
        const float wy1 = fy, wy0 = 1.0f - fy;

        const int r0 = (oy + iy0) * IMG;
        const int r1 = (oy + iy1) * IMG;
        const bool fresh = (iy0 != iy1_prev);     // warp-uniform

        // 4 row pointers; all plane loads below are [ptr + imm]
        const float* __restrict__ a0 = baseA + r0;
        const float* __restrict__ b0 = baseB + r0;
        const float* __restrict__ a1 = baseA + r1;
        const float* __restrict__ b1 = baseB + r1;

        #pragma unroll
        for (int p = 0; p < PH; ++p) {
            // predicated loads: off-predicate issues no request (0 wavefronts)
            const float t0 = fresh ? __ldg(a0 + p * PLANE) : 0.0f;
            const float t1 = fresh ? __ldg(b0 + p * PLANE) : 0.0f;
            const float u0 = __ldg(a1 + p * PLANE);
            const float u1 = __ldg(b1 + p * PLANE);
            const float hb = fmaf(t1, wx1, t0 * wx0);
            const float h0 = fresh ? hb : h1v[p];     // FSEL, no branch
            const float h1 = fmaf(u1, wx1, u0 * wx0);
            h1v[p] = h1;
            __stcs(op + p * OPLANE, fmaf(h1, wy1, h0 * wy0));
        }
        op += S;
        iy1_prev = iy1;
    }
}

extern "C" void kernel_launch(void* const* d_in, const int* in_sizes, int n_in,
                              void* d_out, int out_size)
{
    const float* x       = (const float*)d_in[0];
    const int*   sizes   = (const int*)d_in[1];
    const int*   offsetx = (const int*)d_in[2];
    const int*   offsety = (const int*)d_in[3];
    float* out = (float*)d_out;

    dim3 grid(S / CHUNK, CUTN, NCH / PH);   // 28 x 64 x 2
    dim3 block(S);                          // 224 threads; warp = 32 consecutive j
    make_cutouts_kernel<<<grid, block>>>(x, sizes, offsetx, offsety, out);
}

// round 17
// speedup vs baseline: 1.1299x; 1.1299x over previous
#include <cuda_runtime.h>

// MakeCutouts: 64 cutouts of [4,3,512,512] fp32 -> bilinear 224x224, out [256,3,224,224].
//
// Explicit software pipeline over the row walk (R15/R16 proved ptxas won't do
// this on its own): step k+1's unconditional h1-row tap loads are ISSUED before
// step k's blends/stores, giving them a full consume-phase to cover L2 latency.
// Conditional h0 loads stay at consume time under a warp-uniform branch (the
// select-zero form measured slower in R16).
//
//  - PH=4 planes per block (z-split x3) keeps two in-flight U-sets + h1v under
//    the 56-reg bound=5 cap (PH=6 would spill).
//  - row iy1 strictly increasing -> always fresh; row iy0 reuses previous h1
//    blend when equal to previous iy1 (warp-uniform).
//  - plane loads at immediate offsets; warp = 32 consecutive j -> coalesced
//    __stcs stores; 12.6MB input stays L2-resident vs the 154MB output stream.

#define IMG   512
#define S     224
#define CUTN  64
#define NCH   12
#define PH    4
#define CHUNK 8
#define PLANE (IMG*IMG)
#define OPLANE (S*S)

__global__ __launch_bounds__(S, 5)
void make_cutouts_kernel(const float* __restrict__ x,
                         const int*   __restrict__ sizes,
                         const int*   __restrict__ offsetx,
                         const int*   __restrict__ offsety,
                         float*       __restrict__ out)
{
    const int j     = threadIdx.x;            // output column
    const int i0    = blockIdx.x * CHUNK;     // first output row of this chunk
    const int n     = blockIdx.y;             // cutout
    const int pbase = blockIdx.z * PH;        // plane group (0,4,8)

    const int   size  = __ldg(sizes + n);
    const float scale = (float)size * (1.0f / (float)S);
    const int   ox    = __ldg(offsetx + n);
    const int   oy    = __ldg(offsety + n);
    const int   sm1   = size - 1;

    // column taps (fixed for the whole walk)
    float srcx = fmaxf(scale * ((float)j + 0.5f) - 0.5f, 0.0f);
    int   ix0  = (int)floorf(srcx);
    const float fx = srcx - (float)ix0;       // frac before clamp (matches ref)
    ix0 = min(ix0, sm1);
    const int ix1 = min(ix0 + 1, sm1);
    const float wx1 = fx, wx0 = 1.0f - fx;

    const float* __restrict__ baseA = x + pbase * PLANE + (ox + ix0);
    const float* __restrict__ baseB = x + pbase * PLANE + (ox + ix1);

    float h1v[PH];                            // last blended h1 row, per plane
    float U0[PH], U1[PH];                     // in-flight h1-row taps (current step)

    // ---- pipeline prologue: index + U-prefetch for step 0 ----
    int   c_r0;  bool c_fresh;  float c_wy0, c_wy1;
    {
        float srcy = fmaxf(scale * ((float)i0 + 0.5f) - 0.5f, 0.0f);
        int   iy0  = (int)floorf(srcy);
        const float fy = srcy - (float)iy0;
        iy0 = min(iy0, sm1);
        const int iy1 = min(iy0 + 1, sm1);
        c_wy1 = fy;  c_wy0 = 1.0f - fy;
        c_r0 = (oy + iy0) * IMG;
        c_fresh = true;                        // first step always loads h0
        const int r1 = (oy + iy1) * IMG;
        #pragma unroll
        for (int p = 0; p < PH; ++p) {
            U0[p] = __ldg(baseA + r1 + p * PLANE);
            U1[p] = __ldg(baseB + r1 + p * PLANE);
        }
    }
    int iy1_prev;
    {   // recompute iy1 of step 0 for the fresh-chain (cheap, avoids extra live reg)
        float srcy = fmaxf(scale * ((float)i0 + 0.5f) - 0.5f, 0.0f);
        int   iy0  = min((int)floorf(srcy), sm1);
        iy1_prev   = min(iy0 + 1, sm1);
    }

    float* __restrict__ op = out + ((n * NCH + pbase) * OPLANE + i0 * S + j);

    #pragma unroll
    for (int k = 0; k < CHUNK; ++k) {
        // ---- phase 1: index + U-prefetch for step k+1 (issued BEFORE consume) ----
        float N0[PH], N1[PH];
        int   n_r0 = 0;  bool n_fresh = false;  float n_wy0 = 0.f, n_wy1 = 0.f;
        if (k + 1 < CHUNK) {
            const int i = i0 + k + 1;
            float srcy = fmaxf(scale * ((float)i + 0.5f) - 0.5f, 0.0f);
            int   iy0  = (int)floorf(srcy);
            const float fy = srcy - (float)iy0;
            iy0 = min(iy0, sm1);
            const int iy1 = min(iy0 + 1, sm1);
            n_wy1 = fy;  n_wy0 = 1.0f - fy;
            n_r0 = (oy + iy0) * IMG;
            n_fresh = (iy0 != iy1_prev);
            const int r1 = (oy + iy1) * IMG;
            #pragma unroll
            for (int p = 0; p < PH; ++p) {
                N0[p] = __ldg(baseA + r1 + p * PLANE);
                N1[p] = __ldg(baseB + r1 + p * PLANE);
            }
            iy1_prev = iy1;
        }

        // ---- phase 2: consume step k ----
        if (c_fresh) {                         // warp-uniform branch (R15 form)
            const float* __restrict__ a0 = baseA + c_r0;
            const float* __restrict__ b0 = baseB + c_r0;
            #pragma unroll
            for (int p = 0; p < PH; ++p) {
                const float h0 = fmaf(__ldg(b0 + p * PLANE), wx1,
                                      __ldg(a0 + p * PLANE) * wx0);
                const float h1 = fmaf(U1[p], wx1, U0[p] * wx0);
                h1v[p] = h1;
                __stcs(op + p * OPLANE, fmaf(h1, c_wy1, h0 * c_wy0));
            }
        } else {
            #pragma unroll
            for (int p = 0; p < PH; ++p) {
                const float h0 = h1v[p];
                const float h1 = fmaf(U1[p], wx1, U0[p] * wx0);
                h1v[p] = h1;
                __stcs(op + p * OPLANE, fmaf(h1, c_wy1, h0 * c_wy0));
            }
        }
        op += S;

        // ---- phase 3: rotate ----
        if (k + 1 < CHUNK) {
            #pragma unroll
            for (int p = 0; p < PH; ++p) { U0[p] = N0[p]; U1[p] = N1[p]; }
            c_r0 = n_r0;  c_fresh = n_fresh;  c_wy0 = n_wy0;  c_wy1 = n_wy1;
        }
    }
}

extern "C" void kernel_launch(void* const* d_in, const int* in_sizes, int n_in,
                              void* d_out, int out_size)
{
    const float* x       = (const float*)d_in[0];
    const int*   sizes   = (const int*)d_in[1];
    const int*   offsetx = (const int*)d_in[2];
    const int*   offsety = (const int*)d_in[3];
    float* out = (float*)d_out;

    dim3 grid(S / CHUNK, CUTN, NCH / PH);   // 28 x 64 x 3
    dim3 block(S);                          // 224 threads; warp = 32 consecutive j
    make_cutouts_kernel<<<grid, block>>>(x, sizes, offsetx, offsety, out);
}